// round 1
// baseline (speedup 1.0000x reference)
#include <cuda_runtime.h>
#include <math.h>

#define NN    50000
#define FIN   512
#define HEADS 4
#define HID   64
#define NCLS  40
#define EE    800000
#define ETOT  (EE + NN)      // 850000 (with self loops)
#define D1    (HEADS * HID)  // 256

// ---------------- scratch (device globals; no allocation allowed) ----------
static __device__ float g_h  [(size_t)NN * D1];      // GEMM output h
static __device__ float g_buf[(size_t)NN * D1];      // aggregated output / next input
static __device__ float g_e  [(size_t)ETOT * HEADS]; // edge logits -> alpha
static __device__ float g_as [NN * HEADS];
static __device__ float g_ad [NN * HEADS];
static __device__ int   g_m  [NN * HEADS];           // ordered-int encoded max
static __device__ float g_den[NN * HEADS];

// order-preserving float<->int encoding so atomicMax(int) works on floats
__device__ __forceinline__ int f2oi(float f) {
    int i = __float_as_int(f);
    return i >= 0 ? i : (i ^ 0x7FFFFFFF);
}
__device__ __forceinline__ float oi2f(int i) {
    return __int_as_float(i >= 0 ? i : (i ^ 0x7FFFFFFF));
}

__device__ __forceinline__ void red_add_v4(float* p, float a, float b, float c, float d) {
    asm volatile("red.global.add.v4.f32 [%0], {%1,%2,%3,%4};"
                 :: "l"(p), "f"(a), "f"(b), "f"(c), "f"(d) : "memory");
}

// ---------------- GEMM: C[M,N] = A[M,K] @ W[K,N], fp32, 128x128x8 ----------
__global__ __launch_bounds__(256) void sgemm128(const float* __restrict__ A,
                                                const float* __restrict__ W,
                                                float* __restrict__ C,
                                                int M, int N, int K) {
    __shared__ float As[8][128];   // transposed A tile
    __shared__ float Ws[8][128];
    int tid = threadIdx.x;
    int tx = tid & 15, ty = tid >> 4;
    int bm = blockIdx.x * 128;
    int bn = blockIdx.y * 128;

    float acc[8][8];
#pragma unroll
    for (int i = 0; i < 8; i++)
#pragma unroll
        for (int j = 0; j < 8; j++) acc[i][j] = 0.f;

    int arow = tid >> 1;           // 0..127
    int ac4  = (tid & 1) * 4;      // 0 or 4
    int wrow = tid >> 5;           // 0..7
    int wc4  = (tid & 31) * 4;     // 0..124

    for (int k0 = 0; k0 < K; k0 += 8) {
        float4 av = make_float4(0.f, 0.f, 0.f, 0.f);
        if (bm + arow < M)
            av = *(const float4*)&A[(size_t)(bm + arow) * K + k0 + ac4];
        As[ac4 + 0][arow] = av.x;
        As[ac4 + 1][arow] = av.y;
        As[ac4 + 2][arow] = av.z;
        As[ac4 + 3][arow] = av.w;

        float4 wv = make_float4(0.f, 0.f, 0.f, 0.f);
        if (bn + wc4 < N)   // N is a multiple of 4, so whole float4 is in range
            wv = *(const float4*)&W[(size_t)(k0 + wrow) * N + bn + wc4];
        *(float4*)&Ws[wrow][wc4] = wv;
        __syncthreads();

#pragma unroll
        for (int kk = 0; kk < 8; kk++) {
            float4 a0 = *(const float4*)&As[kk][ty * 8];
            float4 a1 = *(const float4*)&As[kk][ty * 8 + 4];
            float4 w0 = *(const float4*)&Ws[kk][tx * 8];
            float4 w1 = *(const float4*)&Ws[kk][tx * 8 + 4];
            float ar[8] = {a0.x, a0.y, a0.z, a0.w, a1.x, a1.y, a1.z, a1.w};
            float wr[8] = {w0.x, w0.y, w0.z, w0.w, w1.x, w1.y, w1.z, w1.w};
#pragma unroll
            for (int i = 0; i < 8; i++)
#pragma unroll
                for (int j = 0; j < 8; j++) acc[i][j] += ar[i] * wr[j];
        }
        __syncthreads();
    }

#pragma unroll
    for (int i = 0; i < 8; i++) {
        int row = bm + ty * 8 + i;
        int col = bn + tx * 8;
        if (row < M && col < N) {   // N is a multiple of 8, so both float4 in range
            *(float4*)&C[(size_t)row * N + col] =
                make_float4(acc[i][0], acc[i][1], acc[i][2], acc[i][3]);
            *(float4*)&C[(size_t)row * N + col + 4] =
                make_float4(acc[i][4], acc[i][5], acc[i][6], acc[i][7]);
        }
    }
}

// ---------------- per-node: a_s, a_d, init m/den, zero out-buffer ----------
__global__ void node_prep(const float* __restrict__ h,
                          const float* __restrict__ atts,
                          const float* __restrict__ attd,
                          int H, int C, float* __restrict__ obuf) {
    int warp = (blockIdx.x * blockDim.x + threadIdx.x) >> 5;
    int lane = threadIdx.x & 31;
    if (warp >= NN) return;
    int HC = H * C;
    const float* hr = h + (size_t)warp * HC;
    for (int hd = 0; hd < H; hd++) {
        float s = 0.f, d = 0.f;
        for (int c = lane; c < C; c += 32) {
            float v = hr[hd * C + c];
            s += v * atts[hd * C + c];
            d += v * attd[hd * C + c];
        }
#pragma unroll
        for (int o = 16; o; o >>= 1) {
            s += __shfl_down_sync(0xFFFFFFFFu, s, o);
            d += __shfl_down_sync(0xFFFFFFFFu, d, o);
        }
        if (lane == 0) {
            g_as [warp * H + hd] = s;
            g_ad [warp * H + hd] = d;
            g_m  [warp * H + hd] = (int)0x80000000;
            g_den[warp * H + hd] = 0.f;
        }
    }
    float* orow = obuf + (size_t)warp * HC;
    for (int i = lane; i < HC; i += 32) orow[i] = 0.f;
}

// ---------------- edge pass 1: logits + segment max -----------------------
__global__ void edge_max(const int* __restrict__ ei, int H) {
    int idx = blockIdx.x * blockDim.x + threadIdx.x;
    if (idx >= ETOT * H) return;
    int e = idx / H, hd = idx - e * H;
    int s, d;
    if (e < EE) { s = ei[e]; d = ei[EE + e]; }
    else        { s = d = e - EE; }
    float v = g_as[s * H + hd] + g_ad[d * H + hd];
    v = v > 0.f ? v : 0.2f * v;              // leaky_relu(0.2)
    g_e[idx] = v;
    atomicMax(&g_m[d * H + hd], f2oi(v));
}

// ---------------- edge pass 2: exp + segment sum ---------------------------
__global__ void edge_sum(const int* __restrict__ ei, int H) {
    int idx = blockIdx.x * blockDim.x + threadIdx.x;
    if (idx >= ETOT * H) return;
    int e = idx / H, hd = idx - e * H;
    int d;
    if (e < EE) d = ei[EE + e];
    else        d = e - EE;
    float a = expf(g_e[idx] - oi2f(g_m[d * H + hd]));
    g_e[idx] = a;
    atomicAdd(&g_den[d * H + hd], a);
}

// ---------------- edge pass 3: out[dst] += h[src] * alpha ------------------
__global__ void edge_aggr(const int* __restrict__ ei,
                          const float* __restrict__ h,
                          float* __restrict__ obuf,
                          int H, int C) {
    int HC = H * C;
    int per = HC >> 2;                       // float4 groups per edge
    int idx = blockIdx.x * blockDim.x + threadIdx.x;
    int total = ETOT * per;
    if (idx >= total) return;
    int e = idx / per, q = idx - e * per;
    int c = q * 4, hd = c / C;               // C % 4 == 0 -> group stays in head
    int s, d;
    if (e < EE) { s = ei[e]; d = ei[EE + e]; }
    else        { s = d = e - EE; }
    float coef = g_e[e * H + hd] / g_den[d * H + hd];
    float4 hv = *(const float4*)&h[(size_t)s * HC + c];
    red_add_v4(&obuf[(size_t)d * HC + c],
               hv.x * coef, hv.y * coef, hv.z * coef, hv.w * coef);
}

// ---------------- epilogues ------------------------------------------------
__global__ void bias_elu(float* __restrict__ o, const float* __restrict__ b,
                         int HC, int total) {
    int i = blockIdx.x * blockDim.x + threadIdx.x;
    if (i >= total) return;
    float v = o[i] + b[i % HC];
    o[i] = v > 0.f ? v : expm1f(v);
}

__global__ void bias_out(const float* __restrict__ o, const float* __restrict__ b,
                         float* __restrict__ out, int HC, int total) {
    int i = blockIdx.x * blockDim.x + threadIdx.x;
    if (i >= total) return;
    out[i] = o[i] + b[i % HC];
}

// ---------------- driver ----------------------------------------------------
extern "C" void kernel_launch(void* const* d_in, const int* in_sizes, int n_in,
                              void* d_out, int out_size) {
    const float* x   = (const float*)d_in[0];
    const int*   ei  = (const int*)  d_in[1];
    const float* W1  = (const float*)d_in[2];
    const float* as1 = (const float*)d_in[3];
    const float* ad1 = (const float*)d_in[4];
    const float* b1  = (const float*)d_in[5];
    const float* W2  = (const float*)d_in[6];
    const float* as2 = (const float*)d_in[7];
    const float* ad2 = (const float*)d_in[8];
    const float* b2  = (const float*)d_in[9];
    const float* W3  = (const float*)d_in[10];
    const float* as3 = (const float*)d_in[11];
    const float* ad3 = (const float*)d_in[12];
    const float* b3  = (const float*)d_in[13];
    float* out = (float*)d_out;

    float *h, *buf;
    cudaGetSymbolAddress((void**)&h,   g_h);
    cudaGetSymbolAddress((void**)&buf, g_buf);

    const int TB = 256;
    int tEH  = ETOT * HEADS;
    int tAg  = ETOT * (D1 / 4);
    int tE1  = ETOT;
    int tAg3 = ETOT * (NCLS / 4);

    // ---- layer 1: x[NN,FIN] @ W1 -> h[NN,D1]; aggregate -> buf; elu ----
    dim3 g1((NN + 127) / 128, (D1 + 127) / 128);
    sgemm128<<<g1, TB>>>(x, W1, h, NN, D1, FIN);
    node_prep<<<(NN + 7) / 8, TB>>>(h, as1, ad1, HEADS, HID, buf);
    edge_max <<<(tEH + TB - 1) / TB, TB>>>(ei, HEADS);
    edge_sum <<<(tEH + TB - 1) / TB, TB>>>(ei, HEADS);
    edge_aggr<<<(tAg + TB - 1) / TB, TB>>>(ei, h, buf, HEADS, HID);
    bias_elu <<<(NN * D1 + TB - 1) / TB, TB>>>(buf, b1, D1, NN * D1);

    // ---- layer 2: buf @ W2 -> h; aggregate -> buf; elu ----
    sgemm128<<<g1, TB>>>(buf, W2, h, NN, D1, D1);
    node_prep<<<(NN + 7) / 8, TB>>>(h, as2, ad2, HEADS, HID, buf);
    edge_max <<<(tEH + TB - 1) / TB, TB>>>(ei, HEADS);
    edge_sum <<<(tEH + TB - 1) / TB, TB>>>(ei, HEADS);
    edge_aggr<<<(tAg + TB - 1) / TB, TB>>>(ei, h, buf, HEADS, HID);
    bias_elu <<<(NN * D1 + TB - 1) / TB, TB>>>(buf, b2, D1, NN * D1);

    // ---- layer 3: buf @ W3 -> h[NN,NCLS]; aggregate -> buf; + b3 -> out ----
    dim3 g3((NN + 127) / 128, 1);
    sgemm128<<<g3, TB>>>(buf, W3, h, NN, NCLS, D1);
    node_prep<<<(NN + 7) / 8, TB>>>(h, as3, ad3, 1, NCLS, buf);
    edge_max <<<(tE1 + TB - 1) / TB, TB>>>(ei, 1);
    edge_sum <<<(tE1 + TB - 1) / TB, TB>>>(ei, 1);
    edge_aggr<<<(tAg3 + TB - 1) / TB, TB>>>(ei, h, buf, 1, NCLS);
    bias_out <<<(NN * NCLS + TB - 1) / TB, TB>>>(buf, b3, out, NCLS, NN * NCLS);
}

// round 2
// speedup vs baseline: 1.2087x; 1.2087x over previous
#include <cuda_runtime.h>
#include <math.h>

#define NN    50000
#define FIN   512
#define HEADS 4
#define HID   64
#define NCLS  40
#define EE    800000
#define ETOT  (EE + NN)      // 850000 (with self loops)
#define D1    (HEADS * HID)  // 256

// ---------------- scratch (device globals; no allocation allowed) ----------
static __device__ float g_h  [(size_t)NN * D1];      // GEMM output h
static __device__ float g_buf[(size_t)NN * D1];      // aggregated output / next input
static __device__ float g_e  [(size_t)ETOT * HEADS]; // edge logits -> alpha -> coef
static __device__ float g_as [NN * HEADS];
static __device__ float g_ad [NN * HEADS];
static __device__ int   g_m  [NN * HEADS];           // ordered-int encoded max
static __device__ float g_den[NN * HEADS];

// order-preserving float<->int encoding so atomicMax(int) works on floats
__device__ __forceinline__ int f2oi(float f) {
    int i = __float_as_int(f);
    return i >= 0 ? i : (i ^ 0x7FFFFFFF);
}
__device__ __forceinline__ float oi2f(int i) {
    return __int_as_float(i >= 0 ? i : (i ^ 0x7FFFFFFF));
}

__device__ __forceinline__ void red_add_v4(float* p, float a, float b, float c, float d) {
    asm volatile("red.global.add.v4.f32 [%0], {%1,%2,%3,%4};"
                 :: "l"(p), "f"(a), "f"(b), "f"(c), "f"(d) : "memory");
}

// ---------------- tf32 helpers ---------------------------------------------
__device__ __forceinline__ unsigned f2tf(float f) {
    unsigned u;
    asm("cvt.rna.tf32.f32 %0, %1;" : "=r"(u) : "f"(f));
    return u;
}
__device__ __forceinline__ void tf_split(float f, unsigned& hi, unsigned& lo) {
    hi = f2tf(f);
    float r = f - __uint_as_float(hi);
    lo = f2tf(r);
}
__device__ __forceinline__ void mma_tf32(float c[4],
                                         unsigned a0, unsigned a1, unsigned a2, unsigned a3,
                                         unsigned b0, unsigned b1) {
    asm volatile(
        "mma.sync.aligned.m16n8k8.row.col.f32.tf32.tf32.f32 "
        "{%0,%1,%2,%3}, {%4,%5,%6,%7}, {%8,%9}, {%0,%1,%2,%3};"
        : "+f"(c[0]), "+f"(c[1]), "+f"(c[2]), "+f"(c[3])
        : "r"(a0), "r"(a1), "r"(a2), "r"(a3), "r"(b0), "r"(b1));
}

// ---------------- GEMM: C[M,N] = A[M,K] @ W[K,N], 3xTF32 tensor cores ------
// Block tile 128x128, BK=16, 8 warps (2 m x 4 n), warp tile 64x32 of m16n8k8.
#define SA 136   // smem stride (floats), conflict-free fragment loads
#define SB 136
__global__ __launch_bounds__(256) void gemm_tf32(const float* __restrict__ A,
                                                 const float* __restrict__ W,
                                                 float* __restrict__ C,
                                                 int M, int N, int K) {
    __shared__ float As[16][SA];   // [k][m]
    __shared__ float Bs[16][SB];   // [k][n]

    int tid  = threadIdx.x;
    int lane = tid & 31;
    int wid  = tid >> 5;
    int warpM = wid & 1;           // 0..1
    int warpN = wid >> 1;          // 0..3
    int g = lane >> 2, t = lane & 3;

    int bm = blockIdx.x * 128;
    int bn = blockIdx.y * 128;

    float acc[4][4][4];
#pragma unroll
    for (int i = 0; i < 4; i++)
#pragma unroll
        for (int j = 0; j < 4; j++)
#pragma unroll
            for (int q = 0; q < 4; q++) acc[i][j][q] = 0.f;

    // global-load mapping
    int ar  = tid >> 1;            // 0..127 : A row within tile
    int ak4 = (tid & 1) * 8;       // 0 or 8 : A k offset (two float4)
    int bkr = tid >> 4;            // 0..15  : B k row
    int bc8 = (tid & 15) * 8;      // 0..120 : B col offset (two float4)

    for (int k0 = 0; k0 < K; k0 += 16) {
        // A tile: 128 x 16
        {
            int row = bm + ar;
#pragma unroll
            for (int h = 0; h < 2; h++) {
                int kc = ak4 + h * 4;
                float4 v = make_float4(0.f, 0.f, 0.f, 0.f);
                if (row < M)
                    v = *(const float4*)&A[(size_t)row * K + k0 + kc];
                As[kc + 0][ar] = v.x;
                As[kc + 1][ar] = v.y;
                As[kc + 2][ar] = v.z;
                As[kc + 3][ar] = v.w;
            }
        }
        // B tile: 16 x 128
        {
#pragma unroll
            for (int h = 0; h < 2; h++) {
                int c = bc8 + h * 4;
                float4 v = make_float4(0.f, 0.f, 0.f, 0.f);
                if (bn + c + 3 < N)
                    v = *(const float4*)&W[(size_t)(k0 + bkr) * N + bn + c];
                *(float4*)&Bs[bkr][c] = v;
            }
        }
        __syncthreads();

#pragma unroll
        for (int kk = 0; kk < 16; kk += 8) {
            unsigned aHi[4][4], aLo[4][4], bHi[4][2], bLo[4][2];
            int rowb = warpM * 64 + g;
#pragma unroll
            for (int mt = 0; mt < 4; mt++) {
                int r = rowb + mt * 16;
                tf_split(As[kk + t    ][r    ], aHi[mt][0], aLo[mt][0]);
                tf_split(As[kk + t    ][r + 8], aHi[mt][1], aLo[mt][1]);
                tf_split(As[kk + t + 4][r    ], aHi[mt][2], aLo[mt][2]);
                tf_split(As[kk + t + 4][r + 8], aHi[mt][3], aLo[mt][3]);
            }
            int colb = warpN * 32 + g;
#pragma unroll
            for (int nt = 0; nt < 4; nt++) {
                int c = colb + nt * 8;
                tf_split(Bs[kk + t    ][c], bHi[nt][0], bLo[nt][0]);
                tf_split(Bs[kk + t + 4][c], bHi[nt][1], bLo[nt][1]);
            }
#pragma unroll
            for (int mt = 0; mt < 4; mt++)
#pragma unroll
                for (int nt = 0; nt < 4; nt++) {
                    mma_tf32(acc[mt][nt], aHi[mt][0], aHi[mt][1], aHi[mt][2], aHi[mt][3],
                             bLo[nt][0], bLo[nt][1]);
                    mma_tf32(acc[mt][nt], aLo[mt][0], aLo[mt][1], aLo[mt][2], aLo[mt][3],
                             bHi[nt][0], bHi[nt][1]);
                    mma_tf32(acc[mt][nt], aHi[mt][0], aHi[mt][1], aHi[mt][2], aHi[mt][3],
                             bHi[nt][0], bHi[nt][1]);
                }
        }
        __syncthreads();
    }

    // store C
#pragma unroll
    for (int mt = 0; mt < 4; mt++) {
        int row0 = bm + warpM * 64 + mt * 16 + g;
#pragma unroll
        for (int nt = 0; nt < 4; nt++) {
            int col = bn + warpN * 32 + nt * 8 + 2 * t;
            if (col < N) {
                if (row0 < M)
                    *(float2*)&C[(size_t)row0 * N + col] =
                        make_float2(acc[mt][nt][0], acc[mt][nt][1]);
                if (row0 + 8 < M)
                    *(float2*)&C[(size_t)(row0 + 8) * N + col] =
                        make_float2(acc[mt][nt][2], acc[mt][nt][3]);
            }
        }
    }
}

// ---------------- per-node: a_s, a_d, init m/den, zero out-buffer ----------
__global__ void node_prep(const float* __restrict__ h,
                          const float* __restrict__ atts,
                          const float* __restrict__ attd,
                          int H, int C, float* __restrict__ obuf) {
    int warp = (blockIdx.x * blockDim.x + threadIdx.x) >> 5;
    int lane = threadIdx.x & 31;
    if (warp >= NN) return;
    int HC = H * C;
    const float* hr = h + (size_t)warp * HC;
    for (int hd = 0; hd < H; hd++) {
        float s = 0.f, d = 0.f;
        for (int c = lane; c < C; c += 32) {
            float v = hr[hd * C + c];
            s += v * atts[hd * C + c];
            d += v * attd[hd * C + c];
        }
#pragma unroll
        for (int o = 16; o; o >>= 1) {
            s += __shfl_down_sync(0xFFFFFFFFu, s, o);
            d += __shfl_down_sync(0xFFFFFFFFu, d, o);
        }
        if (lane == 0) {
            g_as [warp * H + hd] = s;
            g_ad [warp * H + hd] = d;
            g_m  [warp * H + hd] = (int)0x80000000;
            g_den[warp * H + hd] = 0.f;
        }
    }
    float* orow = obuf + (size_t)warp * HC;
    for (int i = lane; i < HC; i += 32) orow[i] = 0.f;
}

// ---------------- edge pass 1: logits + segment max -----------------------
__global__ void edge_max(const int* __restrict__ ei, int H) {
    int idx = blockIdx.x * blockDim.x + threadIdx.x;
    if (idx >= ETOT * H) return;
    int e = idx / H, hd = idx - e * H;
    int s, d;
    if (e < EE) { s = ei[e]; d = ei[EE + e]; }
    else        { s = d = e - EE; }
    float v = g_as[s * H + hd] + g_ad[d * H + hd];
    v = v > 0.f ? v : 0.2f * v;              // leaky_relu(0.2)
    g_e[idx] = v;
    atomicMax(&g_m[d * H + hd], f2oi(v));
}

// ---------------- edge pass 2: exp + segment sum ---------------------------
__global__ void edge_sum(const int* __restrict__ ei, int H) {
    int idx = blockIdx.x * blockDim.x + threadIdx.x;
    if (idx >= ETOT * H) return;
    int e = idx / H, hd = idx - e * H;
    int d;
    if (e < EE) d = ei[EE + e];
    else        d = e - EE;
    float a = expf(g_e[idx] - oi2f(g_m[d * H + hd]));
    g_e[idx] = a;
    atomicAdd(&g_den[d * H + hd], a);
}

// ---------------- edge pass 2.5: coef = alpha / den -------------------------
__global__ void edge_coef(const int* __restrict__ ei, int H) {
    int idx = blockIdx.x * blockDim.x + threadIdx.x;
    if (idx >= ETOT * H) return;
    int e = idx / H, hd = idx - e * H;
    int d;
    if (e < EE) d = ei[EE + e];
    else        d = e - EE;
    g_e[idx] = g_e[idx] / g_den[d * H + hd];
}

// ---------------- edge pass 3: out[dst] += h[src] * coef -------------------
__global__ void edge_aggr(const int* __restrict__ ei,
                          const float* __restrict__ h,
                          float* __restrict__ obuf,
                          int H, int C) {
    int HC = H * C;
    int per = HC >> 2;                       // float4 groups per edge
    int idx = blockIdx.x * blockDim.x + threadIdx.x;
    int total = ETOT * per;
    if (idx >= total) return;
    int e = idx / per, q = idx - e * per;
    int c = q * 4, hd = c / C;               // C % 4 == 0 -> group stays in head
    int s, d;
    if (e < EE) { s = ei[e]; d = ei[EE + e]; }
    else        { s = d = e - EE; }
    float coef = g_e[e * H + hd];
    float4 hv = *(const float4*)&h[(size_t)s * HC + c];
    red_add_v4(&obuf[(size_t)d * HC + c],
               hv.x * coef, hv.y * coef, hv.z * coef, hv.w * coef);
}

// ---------------- epilogues ------------------------------------------------
__global__ void bias_elu(float* __restrict__ o, const float* __restrict__ b,
                         int HC, int total) {
    int i = blockIdx.x * blockDim.x + threadIdx.x;
    if (i >= total) return;
    float v = o[i] + b[i % HC];
    o[i] = v > 0.f ? v : expm1f(v);
}

__global__ void bias_out(const float* __restrict__ o, const float* __restrict__ b,
                         float* __restrict__ out, int HC, int total) {
    int i = blockIdx.x * blockDim.x + threadIdx.x;
    if (i >= total) return;
    out[i] = o[i] + b[i % HC];
}

// ---------------- driver ----------------------------------------------------
extern "C" void kernel_launch(void* const* d_in, const int* in_sizes, int n_in,
                              void* d_out, int out_size) {
    const float* x   = (const float*)d_in[0];
    const int*   ei  = (const int*)  d_in[1];
    const float* W1  = (const float*)d_in[2];
    const float* as1 = (const float*)d_in[3];
    const float* ad1 = (const float*)d_in[4];
    const float* b1  = (const float*)d_in[5];
    const float* W2  = (const float*)d_in[6];
    const float* as2 = (const float*)d_in[7];
    const float* ad2 = (const float*)d_in[8];
    const float* b2  = (const float*)d_in[9];
    const float* W3  = (const float*)d_in[10];
    const float* as3 = (const float*)d_in[11];
    const float* ad3 = (const float*)d_in[12];
    const float* b3  = (const float*)d_in[13];
    float* out = (float*)d_out;

    float *h, *buf;
    cudaGetSymbolAddress((void**)&h,   g_h);
    cudaGetSymbolAddress((void**)&buf, g_buf);

    const int TB = 256;
    int tEH  = ETOT * HEADS;
    int tAg  = ETOT * (D1 / 4);
    int tE1  = ETOT;
    int tAg3 = ETOT * (NCLS / 4);

    // ---- layer 1: x[NN,FIN] @ W1 -> h[NN,D1]; aggregate -> buf; elu ----
    dim3 g1((NN + 127) / 128, (D1 + 127) / 128);
    gemm_tf32<<<g1, TB>>>(x, W1, h, NN, D1, FIN);
    node_prep<<<(NN + 7) / 8, TB>>>(h, as1, ad1, HEADS, HID, buf);
    edge_max <<<(tEH + TB - 1) / TB, TB>>>(ei, HEADS);
    edge_sum <<<(tEH + TB - 1) / TB, TB>>>(ei, HEADS);
    edge_coef<<<(tEH + TB - 1) / TB, TB>>>(ei, HEADS);
    edge_aggr<<<(tAg + TB - 1) / TB, TB>>>(ei, h, buf, HEADS, HID);
    bias_elu <<<(NN * D1 + TB - 1) / TB, TB>>>(buf, b1, D1, NN * D1);

    // ---- layer 2: buf @ W2 -> h; aggregate -> buf; elu ----
    gemm_tf32<<<g1, TB>>>(buf, W2, h, NN, D1, D1);
    node_prep<<<(NN + 7) / 8, TB>>>(h, as2, ad2, HEADS, HID, buf);
    edge_max <<<(tEH + TB - 1) / TB, TB>>>(ei, HEADS);
    edge_sum <<<(tEH + TB - 1) / TB, TB>>>(ei, HEADS);
    edge_coef<<<(tEH + TB - 1) / TB, TB>>>(ei, HEADS);
    edge_aggr<<<(tAg + TB - 1) / TB, TB>>>(ei, h, buf, HEADS, HID);
    bias_elu <<<(NN * D1 + TB - 1) / TB, TB>>>(buf, b2, D1, NN * D1);

    // ---- layer 3: buf @ W3 -> h[NN,NCLS]; aggregate -> buf; + b3 -> out ----
    dim3 g3((NN + 127) / 128, 1);
    gemm_tf32<<<g3, TB>>>(buf, W3, h, NN, NCLS, D1);
    node_prep<<<(NN + 7) / 8, TB>>>(h, as3, ad3, 1, NCLS, buf);
    edge_max <<<(tE1 + TB - 1) / TB, TB>>>(ei, 1);
    edge_sum <<<(tE1 + TB - 1) / TB, TB>>>(ei, 1);
    edge_coef<<<(tE1 + TB - 1) / TB, TB>>>(ei, 1);
    edge_aggr<<<(tAg3 + TB - 1) / TB, TB>>>(ei, h, buf, 1, NCLS);
    bias_out <<<(NN * NCLS + TB - 1) / TB, TB>>>(buf, b3, out, NCLS, NN * NCLS);
}

// round 3
// speedup vs baseline: 1.4462x; 1.1965x over previous
#include <cuda_runtime.h>
#include <math.h>

#define NN    50000
#define FIN   512
#define HEADS 4
#define HID   64
#define NCLS  40
#define EE    800000
#define ETOT  (EE + NN)      // 850000 (with self loops)
#define D1    (HEADS * HID)  // 256

// ---------------- scratch (device globals; no allocation allowed) ----------
static __device__ float g_h  [(size_t)NN * D1];      // GEMM output h
static __device__ float g_buf[(size_t)NN * D1];      // aggregated output / next input
static __device__ float g_e  [(size_t)ETOT * HEADS]; // per-edge attention coef
static __device__ float g_as [NN * HEADS];
static __device__ float g_ad [NN * HEADS];
static __device__ int   g_deg[NN];
static __device__ int   g_off[NN + 1];
static __device__ int   g_cur[NN];
static __device__ int   g_csr[ETOT];                 // edge ids grouped by dst

// ---------------- tf32 helpers ---------------------------------------------
__device__ __forceinline__ unsigned f2tf(float f) {
    unsigned u;
    asm("cvt.rna.tf32.f32 %0, %1;" : "=r"(u) : "f"(f));
    return u;
}
__device__ __forceinline__ void tf_split(float f, unsigned& hi, unsigned& lo) {
    hi = f2tf(f);
    float r = f - __uint_as_float(hi);
    lo = f2tf(r);
}
__device__ __forceinline__ void mma_tf32(float c[4],
                                         unsigned a0, unsigned a1, unsigned a2, unsigned a3,
                                         unsigned b0, unsigned b1) {
    asm volatile(
        "mma.sync.aligned.m16n8k8.row.col.f32.tf32.tf32.f32 "
        "{%0,%1,%2,%3}, {%4,%5,%6,%7}, {%8,%9}, {%0,%1,%2,%3};"
        : "+f"(c[0]), "+f"(c[1]), "+f"(c[2]), "+f"(c[3])
        : "r"(a0), "r"(a1), "r"(a2), "r"(a3), "r"(b0), "r"(b1));
}

// ---------------- GEMM: C[M,N] = A[M,K] @ W[K,N], 3xTF32 tensor cores ------
#define SA 136
#define SB 136
__global__ __launch_bounds__(256) void gemm_tf32(const float* __restrict__ A,
                                                 const float* __restrict__ W,
                                                 float* __restrict__ C,
                                                 int M, int N, int K) {
    __shared__ float As[16][SA];   // [k][m]
    __shared__ float Bs[16][SB];   // [k][n]

    int tid  = threadIdx.x;
    int lane = tid & 31;
    int wid  = tid >> 5;
    int warpM = wid & 1;
    int warpN = wid >> 1;
    int g = lane >> 2, t = lane & 3;

    int bm = blockIdx.x * 128;
    int bn = blockIdx.y * 128;

    float acc[4][4][4];
#pragma unroll
    for (int i = 0; i < 4; i++)
#pragma unroll
        for (int j = 0; j < 4; j++)
#pragma unroll
            for (int q = 0; q < 4; q++) acc[i][j][q] = 0.f;

    int ar  = tid >> 1;
    int ak4 = (tid & 1) * 8;
    int bkr = tid >> 4;
    int bc8 = (tid & 15) * 8;

    for (int k0 = 0; k0 < K; k0 += 16) {
        {
            int row = bm + ar;
#pragma unroll
            for (int h = 0; h < 2; h++) {
                int kc = ak4 + h * 4;
                float4 v = make_float4(0.f, 0.f, 0.f, 0.f);
                if (row < M)
                    v = *(const float4*)&A[(size_t)row * K + k0 + kc];
                As[kc + 0][ar] = v.x;
                As[kc + 1][ar] = v.y;
                As[kc + 2][ar] = v.z;
                As[kc + 3][ar] = v.w;
            }
        }
        {
#pragma unroll
            for (int h = 0; h < 2; h++) {
                int c = bc8 + h * 4;
                float4 v = make_float4(0.f, 0.f, 0.f, 0.f);
                if (bn + c + 3 < N)
                    v = *(const float4*)&W[(size_t)(k0 + bkr) * N + bn + c];
                *(float4*)&Bs[bkr][c] = v;
            }
        }
        __syncthreads();

#pragma unroll
        for (int kk = 0; kk < 16; kk += 8) {
            unsigned aHi[4][4], aLo[4][4], bHi[4][2], bLo[4][2];
            int rowb = warpM * 64 + g;
#pragma unroll
            for (int mt = 0; mt < 4; mt++) {
                int r = rowb + mt * 16;
                tf_split(As[kk + t    ][r    ], aHi[mt][0], aLo[mt][0]);
                tf_split(As[kk + t    ][r + 8], aHi[mt][1], aLo[mt][1]);
                tf_split(As[kk + t + 4][r    ], aHi[mt][2], aLo[mt][2]);
                tf_split(As[kk + t + 4][r + 8], aHi[mt][3], aLo[mt][3]);
            }
            int colb = warpN * 32 + g;
#pragma unroll
            for (int nt = 0; nt < 4; nt++) {
                int c = colb + nt * 8;
                tf_split(Bs[kk + t    ][c], bHi[nt][0], bLo[nt][0]);
                tf_split(Bs[kk + t + 4][c], bHi[nt][1], bLo[nt][1]);
            }
#pragma unroll
            for (int mt = 0; mt < 4; mt++)
#pragma unroll
                for (int nt = 0; nt < 4; nt++) {
                    mma_tf32(acc[mt][nt], aHi[mt][0], aHi[mt][1], aHi[mt][2], aHi[mt][3],
                             bLo[nt][0], bLo[nt][1]);
                    mma_tf32(acc[mt][nt], aLo[mt][0], aLo[mt][1], aLo[mt][2], aLo[mt][3],
                             bHi[nt][0], bHi[nt][1]);
                    mma_tf32(acc[mt][nt], aHi[mt][0], aHi[mt][1], aHi[mt][2], aHi[mt][3],
                             bHi[nt][0], bHi[nt][1]);
                }
        }
        __syncthreads();
    }

#pragma unroll
    for (int mt = 0; mt < 4; mt++) {
        int row0 = bm + warpM * 64 + mt * 16 + g;
#pragma unroll
        for (int nt = 0; nt < 4; nt++) {
            int col = bn + warpN * 32 + nt * 8 + 2 * t;
            if (col < N) {
                if (row0 < M)
                    *(float2*)&C[(size_t)row0 * N + col] =
                        make_float2(acc[mt][nt][0], acc[mt][nt][1]);
                if (row0 + 8 < M)
                    *(float2*)&C[(size_t)(row0 + 8) * N + col] =
                        make_float2(acc[mt][nt][2], acc[mt][nt][3]);
            }
        }
    }
}

// ---------------- CSR build --------------------------------------------------
__global__ void k_zero_deg() {
    int i = blockIdx.x * blockDim.x + threadIdx.x;
    if (i < NN) g_deg[i] = 0;
}

__global__ void k_count(const int* __restrict__ ei) {
    int e = blockIdx.x * blockDim.x + threadIdx.x;
    if (e >= ETOT) return;
    int d = e < EE ? ei[EE + e] : e - EE;
    atomicAdd(&g_deg[d], 1);
}

__global__ __launch_bounds__(1024) void k_scan() {
    __shared__ int part[1024];
    const int SEG = (NN + 1023) / 1024;
    int t = threadIdx.x;
    int lo = t * SEG, hi = min(NN, lo + SEG);
    int s = 0;
    for (int i = lo; i < hi; i++) s += g_deg[i];
    part[t] = s;
    __syncthreads();
    for (int off = 1; off < 1024; off <<= 1) {
        int v = 0;
        if (t >= off) v = part[t - off];
        __syncthreads();
        if (t >= off) part[t] += v;
        __syncthreads();
    }
    int run = t ? part[t - 1] : 0;
    for (int i = lo; i < hi; i++) {
        g_off[i] = run;
        g_cur[i] = run;
        run += g_deg[i];
    }
    if (t == 0) g_off[NN] = part[1023];
}

__global__ void k_scatter(const int* __restrict__ ei) {
    int e = blockIdx.x * blockDim.x + threadIdx.x;
    if (e >= ETOT) return;
    int d = e < EE ? ei[EE + e] : e - EE;
    int pos = atomicAdd(&g_cur[d], 1);
    g_csr[pos] = e;
}

// ---------------- per-node: a_s, a_d -----------------------------------------
__global__ void node_prep(const float* __restrict__ h,
                          const float* __restrict__ atts,
                          const float* __restrict__ attd,
                          int H, int C) {
    int warp = (blockIdx.x * blockDim.x + threadIdx.x) >> 5;
    int lane = threadIdx.x & 31;
    if (warp >= NN) return;
    int HC = H * C;
    const float* hr = h + (size_t)warp * HC;
    for (int hd = 0; hd < H; hd++) {
        float s = 0.f, d = 0.f;
        for (int c = lane; c < C; c += 32) {
            float v = hr[hd * C + c];
            s += v * atts[hd * C + c];
            d += v * attd[hd * C + c];
        }
#pragma unroll
        for (int o = 16; o; o >>= 1) {
            s += __shfl_down_sync(0xFFFFFFFFu, s, o);
            d += __shfl_down_sync(0xFFFFFFFFu, d, o);
        }
        if (lane == 0) {
            g_as[warp * H + hd] = s;
            g_ad[warp * H + hd] = d;
        }
    }
}

// ---------------- fused scatter-softmax: one warp per dst node ---------------
__global__ __launch_bounds__(256) void attn_coef4(const int* __restrict__ ei) {
    int node = (blockIdx.x * blockDim.x + threadIdx.x) >> 5;
    int lane = threadIdx.x & 31;
    if (node >= NN) return;
    int beg = g_off[node];
    int deg = g_off[node + 1] - beg;

    float4 adv = *(const float4*)&g_ad[node * 4];
    float mx0 = -1e30f, mx1 = -1e30f, mx2 = -1e30f, mx3 = -1e30f;

    for (int base = 0; base < deg; base += 32) {
        int i = base + lane;
        if (i < deg) {
            int eid = g_csr[beg + i];
            int s = eid < EE ? ei[eid] : eid - EE;
            float4 av = *(const float4*)&g_as[s * 4];
            float v0 = av.x + adv.x, v1 = av.y + adv.y;
            float v2 = av.z + adv.z, v3 = av.w + adv.w;
            v0 = v0 > 0.f ? v0 : 0.2f * v0;
            v1 = v1 > 0.f ? v1 : 0.2f * v1;
            v2 = v2 > 0.f ? v2 : 0.2f * v2;
            v3 = v3 > 0.f ? v3 : 0.2f * v3;
            mx0 = fmaxf(mx0, v0); mx1 = fmaxf(mx1, v1);
            mx2 = fmaxf(mx2, v2); mx3 = fmaxf(mx3, v3);
        }
    }
#pragma unroll
    for (int o = 16; o; o >>= 1) {
        mx0 = fmaxf(mx0, __shfl_xor_sync(0xFFFFFFFFu, mx0, o));
        mx1 = fmaxf(mx1, __shfl_xor_sync(0xFFFFFFFFu, mx1, o));
        mx2 = fmaxf(mx2, __shfl_xor_sync(0xFFFFFFFFu, mx2, o));
        mx3 = fmaxf(mx3, __shfl_xor_sync(0xFFFFFFFFu, mx3, o));
    }
    float s0 = 0.f, s1 = 0.f, s2 = 0.f, s3 = 0.f;
    for (int base = 0; base < deg; base += 32) {
        int i = base + lane;
        if (i < deg) {
            int eid = g_csr[beg + i];
            int s = eid < EE ? ei[eid] : eid - EE;
            float4 av = *(const float4*)&g_as[s * 4];
            float v0 = av.x + adv.x, v1 = av.y + adv.y;
            float v2 = av.z + adv.z, v3 = av.w + adv.w;
            v0 = v0 > 0.f ? v0 : 0.2f * v0;
            v1 = v1 > 0.f ? v1 : 0.2f * v1;
            v2 = v2 > 0.f ? v2 : 0.2f * v2;
            v3 = v3 > 0.f ? v3 : 0.2f * v3;
            float a0 = __expf(v0 - mx0), a1 = __expf(v1 - mx1);
            float a2 = __expf(v2 - mx2), a3 = __expf(v3 - mx3);
            *(float4*)&g_e[(size_t)eid * 4] = make_float4(a0, a1, a2, a3);
            s0 += a0; s1 += a1; s2 += a2; s3 += a3;
        }
    }
#pragma unroll
    for (int o = 16; o; o >>= 1) {
        s0 += __shfl_xor_sync(0xFFFFFFFFu, s0, o);
        s1 += __shfl_xor_sync(0xFFFFFFFFu, s1, o);
        s2 += __shfl_xor_sync(0xFFFFFFFFu, s2, o);
        s3 += __shfl_xor_sync(0xFFFFFFFFu, s3, o);
    }
    float r0 = 1.f / s0, r1 = 1.f / s1, r2 = 1.f / s2, r3 = 1.f / s3;
    for (int base = 0; base < deg; base += 32) {
        int i = base + lane;
        if (i < deg) {
            int eid = g_csr[beg + i];
            float4 a = *(const float4*)&g_e[(size_t)eid * 4];
            *(float4*)&g_e[(size_t)eid * 4] =
                make_float4(a.x * r0, a.y * r1, a.z * r2, a.w * r3);
        }
    }
}

__global__ __launch_bounds__(256) void attn_coef1(const int* __restrict__ ei) {
    int node = (blockIdx.x * blockDim.x + threadIdx.x) >> 5;
    int lane = threadIdx.x & 31;
    if (node >= NN) return;
    int beg = g_off[node];
    int deg = g_off[node + 1] - beg;

    float adv = g_ad[node];
    float mx = -1e30f;
    for (int base = 0; base < deg; base += 32) {
        int i = base + lane;
        if (i < deg) {
            int eid = g_csr[beg + i];
            int s = eid < EE ? ei[eid] : eid - EE;
            float v = g_as[s] + adv;
            v = v > 0.f ? v : 0.2f * v;
            mx = fmaxf(mx, v);
        }
    }
#pragma unroll
    for (int o = 16; o; o >>= 1) mx = fmaxf(mx, __shfl_xor_sync(0xFFFFFFFFu, mx, o));
    float sm = 0.f;
    for (int base = 0; base < deg; base += 32) {
        int i = base + lane;
        if (i < deg) {
            int eid = g_csr[beg + i];
            int s = eid < EE ? ei[eid] : eid - EE;
            float v = g_as[s] + adv;
            v = v > 0.f ? v : 0.2f * v;
            float a = __expf(v - mx);
            g_e[eid] = a;
            sm += a;
        }
    }
#pragma unroll
    for (int o = 16; o; o >>= 1) sm += __shfl_xor_sync(0xFFFFFFFFu, sm, o);
    float r = 1.f / sm;
    for (int base = 0; base < deg; base += 32) {
        int i = base + lane;
        if (i < deg) {
            int eid = g_csr[beg + i];
            g_e[eid] *= r;
        }
    }
}

// ---------------- aggregation: one warp per dst node, 256 channels ----------
__global__ __launch_bounds__(256) void aggr256(const int* __restrict__ ei,
                                               const float* __restrict__ h,
                                               const float* __restrict__ bias,
                                               float* __restrict__ obuf,
                                               int apply_elu) {
    int node = (blockIdx.x * blockDim.x + threadIdx.x) >> 5;
    int lane = threadIdx.x & 31;
    if (node >= NN) return;
    int beg = g_off[node];
    int deg = g_off[node + 1] - beg;
    int c  = lane * 8;
    int hd = lane >> 3;

    float4 a0 = make_float4(0.f, 0.f, 0.f, 0.f);
    float4 a1 = make_float4(0.f, 0.f, 0.f, 0.f);

    int eid = 0, s = 0;
    if (deg > 0) {
        eid = g_csr[beg];
        s = eid < EE ? ei[eid] : eid - EE;
    }
    for (int i = 0; i < deg; i++) {
        int ce = eid, cs = s;
        if (i + 1 < deg) {
            eid = g_csr[beg + i + 1];
            s = eid < EE ? ei[eid] : eid - EE;
        }
        float coef = g_e[(size_t)ce * 4 + hd];
        const float4* hp = (const float4*)(h + (size_t)cs * 256 + c);
        float4 v0 = hp[0], v1 = hp[1];
        a0.x += coef * v0.x; a0.y += coef * v0.y;
        a0.z += coef * v0.z; a0.w += coef * v0.w;
        a1.x += coef * v1.x; a1.y += coef * v1.y;
        a1.z += coef * v1.z; a1.w += coef * v1.w;
    }
    float4 b0 = *(const float4*)&bias[c];
    float4 b1 = *(const float4*)&bias[c + 4];
    a0.x += b0.x; a0.y += b0.y; a0.z += b0.z; a0.w += b0.w;
    a1.x += b1.x; a1.y += b1.y; a1.z += b1.z; a1.w += b1.w;
    if (apply_elu) {
        a0.x = a0.x > 0.f ? a0.x : expm1f(a0.x);
        a0.y = a0.y > 0.f ? a0.y : expm1f(a0.y);
        a0.z = a0.z > 0.f ? a0.z : expm1f(a0.z);
        a0.w = a0.w > 0.f ? a0.w : expm1f(a0.w);
        a1.x = a1.x > 0.f ? a1.x : expm1f(a1.x);
        a1.y = a1.y > 0.f ? a1.y : expm1f(a1.y);
        a1.z = a1.z > 0.f ? a1.z : expm1f(a1.z);
        a1.w = a1.w > 0.f ? a1.w : expm1f(a1.w);
    }
    float4* op = (float4*)(obuf + (size_t)node * 256 + c);
    op[0] = a0;
    op[1] = a1;
}

// ---------------- aggregation, layer 3: 40 channels, H=1 ---------------------
__global__ __launch_bounds__(256) void aggr40(const int* __restrict__ ei,
                                              const float* __restrict__ h,
                                              const float* __restrict__ bias,
                                              float* __restrict__ out) {
    int node = (blockIdx.x * blockDim.x + threadIdx.x) >> 5;
    int lane = threadIdx.x & 31;
    if (node >= NN) return;
    int beg = g_off[node];
    int deg = g_off[node + 1] - beg;

    float4 acc = make_float4(0.f, 0.f, 0.f, 0.f);
    int c = lane * 4;
    bool act = lane < 10;

    int eid = 0, s = 0;
    if (deg > 0) {
        eid = g_csr[beg];
        s = eid < EE ? ei[eid] : eid - EE;
    }
    for (int i = 0; i < deg; i++) {
        int ce = eid, cs = s;
        if (i + 1 < deg) {
            eid = g_csr[beg + i + 1];
            s = eid < EE ? ei[eid] : eid - EE;
        }
        float coef = g_e[ce];
        if (act) {
            float4 v = *(const float4*)(h + (size_t)cs * 40 + c);
            acc.x += coef * v.x; acc.y += coef * v.y;
            acc.z += coef * v.z; acc.w += coef * v.w;
        }
    }
    if (act) {
        float4 b = *(const float4*)&bias[c];
        acc.x += b.x; acc.y += b.y; acc.z += b.z; acc.w += b.w;
        *(float4*)(out + (size_t)node * 40 + c) = acc;
    }
}

// ---------------- driver ----------------------------------------------------
extern "C" void kernel_launch(void* const* d_in, const int* in_sizes, int n_in,
                              void* d_out, int out_size) {
    const float* x   = (const float*)d_in[0];
    const int*   ei  = (const int*)  d_in[1];
    const float* W1  = (const float*)d_in[2];
    const float* as1 = (const float*)d_in[3];
    const float* ad1 = (const float*)d_in[4];
    const float* b1  = (const float*)d_in[5];
    const float* W2  = (const float*)d_in[6];
    const float* as2 = (const float*)d_in[7];
    const float* ad2 = (const float*)d_in[8];
    const float* b2  = (const float*)d_in[9];
    const float* W3  = (const float*)d_in[10];
    const float* as3 = (const float*)d_in[11];
    const float* ad3 = (const float*)d_in[12];
    const float* b3  = (const float*)d_in[13];
    float* out = (float*)d_out;

    float *h, *buf;
    cudaGetSymbolAddress((void**)&h,   g_h);
    cudaGetSymbolAddress((void**)&buf, g_buf);

    const int TB = 256;
    int gE = (ETOT + TB - 1) / TB;
    int gW = (NN * 32 + TB - 1) / TB;   // one warp per node

    // ---- CSR by dst (edge structure shared by all layers) ----
    k_zero_deg<<<(NN + TB - 1) / TB, TB>>>();
    k_count  <<<gE, TB>>>(ei);
    k_scan   <<<1, 1024>>>();
    k_scatter<<<gE, TB>>>(ei);

    // ---- layer 1 ----
    dim3 g1((NN + 127) / 128, (D1 + 127) / 128);
    gemm_tf32 <<<g1, TB>>>(x, W1, h, NN, D1, FIN);
    node_prep <<<gW, TB>>>(h, as1, ad1, HEADS, HID);
    attn_coef4<<<gW, TB>>>(ei);
    aggr256   <<<gW, TB>>>(ei, h, b1, buf, 1);

    // ---- layer 2 ----
    gemm_tf32 <<<g1, TB>>>(buf, W2, h, NN, D1, D1);
    node_prep <<<gW, TB>>>(h, as2, ad2, HEADS, HID);
    attn_coef4<<<gW, TB>>>(ei);
    aggr256   <<<gW, TB>>>(ei, h, b2, buf, 1);

    // ---- layer 3 ----
    dim3 g3((NN + 127) / 128, 1);
    gemm_tf32 <<<g3, TB>>>(buf, W3, h, NN, NCLS, D1);
    node_prep <<<gW, TB>>>(h, as3, ad3, 1, NCLS);
    attn_coef1<<<gW, TB>>>(ei);
    aggr40    <<<gW, TB>>>(ei, h, b3, out);
}

// round 4
// speedup vs baseline: 1.6767x; 1.1594x over previous
#include <cuda_runtime.h>
#include <math.h>

#define NN    50000
#define FIN   512
#define HEADS 4
#define HID   64
#define NCLS  40
#define EE    800000
#define ETOT  (EE + NN)      // 850000 (with self loops)
#define D1    (HEADS * HID)  // 256

// ---------------- scratch (device globals; no allocation allowed) ----------
static __device__ float g_h  [(size_t)NN * D1];      // GEMM output h
static __device__ float g_buf[(size_t)NN * D1];      // aggregated output / next input
static __device__ float g_e  [(size_t)ETOT * HEADS]; // unnormalized alpha, CSR order
static __device__ float g_as [NN * HEADS];
static __device__ float g_ad [NN * HEADS];
static __device__ float g_r  [NN * HEADS];           // 1/denominator per node,head
static __device__ int   g_deg[NN];
static __device__ int   g_off[NN + 1];
static __device__ int   g_cur[NN];
static __device__ int   g_srcs[ETOT];                // src node ids grouped by dst

// ---------------- tf32 helpers ---------------------------------------------
__device__ __forceinline__ unsigned f2tf(float f) {
    unsigned u;
    asm("cvt.rna.tf32.f32 %0, %1;" : "=r"(u) : "f"(f));
    return u;
}
__device__ __forceinline__ void tf_split(float f, unsigned& hi, unsigned& lo) {
    hi = f2tf(f);
    float r = f - __uint_as_float(hi);
    lo = f2tf(r);
}
__device__ __forceinline__ void mma_tf32(float c[4],
                                         unsigned a0, unsigned a1, unsigned a2, unsigned a3,
                                         unsigned b0, unsigned b1) {
    asm volatile(
        "mma.sync.aligned.m16n8k8.row.col.f32.tf32.tf32.f32 "
        "{%0,%1,%2,%3}, {%4,%5,%6,%7}, {%8,%9}, {%0,%1,%2,%3};"
        : "+f"(c[0]), "+f"(c[1]), "+f"(c[2]), "+f"(c[3])
        : "r"(a0), "r"(a1), "r"(a2), "r"(a3), "r"(b0), "r"(b1));
}

// ---------------- GEMM: C[M,N] = A[M,K] @ W[K,N], 3xTF32 tensor cores ------
#define SA 136
#define SB 136
__global__ __launch_bounds__(256) void gemm_tf32(const float* __restrict__ A,
                                                 const float* __restrict__ W,
                                                 float* __restrict__ C,
                                                 int M, int N, int K) {
    __shared__ float As[16][SA];   // [k][m]
    __shared__ float Bs[16][SB];   // [k][n]

    int tid  = threadIdx.x;
    int lane = tid & 31;
    int wid  = tid >> 5;
    int warpM = wid & 1;
    int warpN = wid >> 1;
    int g = lane >> 2, t = lane & 3;

    int bm = blockIdx.x * 128;
    int bn = blockIdx.y * 128;

    float acc[4][4][4];
#pragma unroll
    for (int i = 0; i < 4; i++)
#pragma unroll
        for (int j = 0; j < 4; j++)
#pragma unroll
            for (int q = 0; q < 4; q++) acc[i][j][q] = 0.f;

    int ar  = tid >> 1;
    int ak4 = (tid & 1) * 8;
    int bkr = tid >> 4;
    int bc8 = (tid & 15) * 8;

    for (int k0 = 0; k0 < K; k0 += 16) {
        {
            int row = bm + ar;
#pragma unroll
            for (int h = 0; h < 2; h++) {
                int kc = ak4 + h * 4;
                float4 v = make_float4(0.f, 0.f, 0.f, 0.f);
                if (row < M)
                    v = *(const float4*)&A[(size_t)row * K + k0 + kc];
                As[kc + 0][ar] = v.x;
                As[kc + 1][ar] = v.y;
                As[kc + 2][ar] = v.z;
                As[kc + 3][ar] = v.w;
            }
        }
        {
#pragma unroll
            for (int h = 0; h < 2; h++) {
                int c = bc8 + h * 4;
                float4 v = make_float4(0.f, 0.f, 0.f, 0.f);
                if (bn + c + 3 < N)
                    v = *(const float4*)&W[(size_t)(k0 + bkr) * N + bn + c];
                *(float4*)&Bs[bkr][c] = v;
            }
        }
        __syncthreads();

#pragma unroll
        for (int kk = 0; kk < 16; kk += 8) {
            unsigned aHi[4][4], aLo[4][4], bHi[4][2], bLo[4][2];
            int rowb = warpM * 64 + g;
#pragma unroll
            for (int mt = 0; mt < 4; mt++) {
                int r = rowb + mt * 16;
                tf_split(As[kk + t    ][r    ], aHi[mt][0], aLo[mt][0]);
                tf_split(As[kk + t    ][r + 8], aHi[mt][1], aLo[mt][1]);
                tf_split(As[kk + t + 4][r    ], aHi[mt][2], aLo[mt][2]);
                tf_split(As[kk + t + 4][r + 8], aHi[mt][3], aLo[mt][3]);
            }
            int colb = warpN * 32 + g;
#pragma unroll
            for (int nt = 0; nt < 4; nt++) {
                int c = colb + nt * 8;
                tf_split(Bs[kk + t    ][c], bHi[nt][0], bLo[nt][0]);
                tf_split(Bs[kk + t + 4][c], bHi[nt][1], bLo[nt][1]);
            }
#pragma unroll
            for (int mt = 0; mt < 4; mt++)
#pragma unroll
                for (int nt = 0; nt < 4; nt++) {
                    mma_tf32(acc[mt][nt], aHi[mt][0], aHi[mt][1], aHi[mt][2], aHi[mt][3],
                             bLo[nt][0], bLo[nt][1]);
                    mma_tf32(acc[mt][nt], aLo[mt][0], aLo[mt][1], aLo[mt][2], aLo[mt][3],
                             bHi[nt][0], bHi[nt][1]);
                    mma_tf32(acc[mt][nt], aHi[mt][0], aHi[mt][1], aHi[mt][2], aHi[mt][3],
                             bHi[nt][0], bHi[nt][1]);
                }
        }
        __syncthreads();
    }

#pragma unroll
    for (int mt = 0; mt < 4; mt++) {
        int row0 = bm + warpM * 64 + mt * 16 + g;
#pragma unroll
        for (int nt = 0; nt < 4; nt++) {
            int col = bn + warpN * 32 + nt * 8 + 2 * t;
            if (col < N) {
                if (row0 < M)
                    *(float2*)&C[(size_t)row0 * N + col] =
                        make_float2(acc[mt][nt][0], acc[mt][nt][1]);
                if (row0 + 8 < M)
                    *(float2*)&C[(size_t)(row0 + 8) * N + col] =
                        make_float2(acc[mt][nt][2], acc[mt][nt][3]);
            }
        }
    }
}

// ---------------- CSR build --------------------------------------------------
__global__ void k_zero_deg() {
    int i = blockIdx.x * blockDim.x + threadIdx.x;
    if (i < NN) g_deg[i] = 0;
}

__global__ void k_count(const int* __restrict__ ei) {
    int e = blockIdx.x * blockDim.x + threadIdx.x;
    if (e >= ETOT) return;
    int d = e < EE ? ei[EE + e] : e - EE;
    atomicAdd(&g_deg[d], 1);
}

__global__ __launch_bounds__(1024) void k_scan() {
    __shared__ int part[1024];
    const int SEG = (NN + 1023) / 1024;
    int t = threadIdx.x;
    int lo = t * SEG, hi = min(NN, lo + SEG);
    int s = 0;
    for (int i = lo; i < hi; i++) s += g_deg[i];
    part[t] = s;
    __syncthreads();
    for (int off = 1; off < 1024; off <<= 1) {
        int v = 0;
        if (t >= off) v = part[t - off];
        __syncthreads();
        if (t >= off) part[t] += v;
        __syncthreads();
    }
    int run = t ? part[t - 1] : 0;
    for (int i = lo; i < hi; i++) {
        g_off[i] = run;
        g_cur[i] = run;
        run += g_deg[i];
    }
    if (t == 0) g_off[NN] = part[1023];
}

__global__ void k_scatter(const int* __restrict__ ei) {
    int e = blockIdx.x * blockDim.x + threadIdx.x;
    if (e >= ETOT) return;
    int s, d;
    if (e < EE) { s = ei[e]; d = ei[EE + e]; }
    else        { s = d = e - EE; }
    int pos = atomicAdd(&g_cur[d], 1);
    g_srcs[pos] = s;
}

// ---------------- per-node: a_s, a_d -----------------------------------------
__global__ void node_prep(const float* __restrict__ h,
                          const float* __restrict__ atts,
                          const float* __restrict__ attd,
                          int H, int C) {
    int warp = (blockIdx.x * blockDim.x + threadIdx.x) >> 5;
    int lane = threadIdx.x & 31;
    if (warp >= NN) return;
    int HC = H * C;
    const float* hr = h + (size_t)warp * HC;
    for (int hd = 0; hd < H; hd++) {
        float s = 0.f, d = 0.f;
        for (int c = lane; c < C; c += 32) {
            float v = hr[hd * C + c];
            s += v * atts[hd * C + c];
            d += v * attd[hd * C + c];
        }
#pragma unroll
        for (int o = 16; o; o >>= 1) {
            s += __shfl_down_sync(0xFFFFFFFFu, s, o);
            d += __shfl_down_sync(0xFFFFFFFFu, d, o);
        }
        if (lane == 0) {
            g_as[warp * H + hd] = s;
            g_ad[warp * H + hd] = d;
        }
    }
}

// ---------------- softmax coefs (H=4): one warp per dst node -----------------
// Writes unnormalized exp(v - max) in CSR order, and 1/sum to g_r.
__global__ __launch_bounds__(256) void attn_coef4() {
    int node = (blockIdx.x * blockDim.x + threadIdx.x) >> 5;
    int lane = threadIdx.x & 31;
    if (node >= NN) return;
    int beg = g_off[node];
    int deg = g_off[node + 1] - beg;

    float4 adv = *(const float4*)&g_ad[node * 4];
    float mx0 = -1e30f, mx1 = -1e30f, mx2 = -1e30f, mx3 = -1e30f;

    // first 32 edges cached in registers (covers most nodes)
    float c0 = 0.f, c1 = 0.f, c2 = 0.f, c3 = 0.f;
    bool have = lane < deg;
    if (have) {
        int s = g_srcs[beg + lane];
        float4 av = *(const float4*)&g_as[s * 4];
        c0 = av.x + adv.x; c1 = av.y + adv.y;
        c2 = av.z + adv.z; c3 = av.w + adv.w;
        c0 = c0 > 0.f ? c0 : 0.2f * c0;
        c1 = c1 > 0.f ? c1 : 0.2f * c1;
        c2 = c2 > 0.f ? c2 : 0.2f * c2;
        c3 = c3 > 0.f ? c3 : 0.2f * c3;
        mx0 = c0; mx1 = c1; mx2 = c2; mx3 = c3;
    }
    for (int base = 32; base < deg; base += 32) {
        int i = base + lane;
        if (i < deg) {
            int s = g_srcs[beg + i];
            float4 av = *(const float4*)&g_as[s * 4];
            float v0 = av.x + adv.x, v1 = av.y + adv.y;
            float v2 = av.z + adv.z, v3 = av.w + adv.w;
            v0 = v0 > 0.f ? v0 : 0.2f * v0;
            v1 = v1 > 0.f ? v1 : 0.2f * v1;
            v2 = v2 > 0.f ? v2 : 0.2f * v2;
            v3 = v3 > 0.f ? v3 : 0.2f * v3;
            mx0 = fmaxf(mx0, v0); mx1 = fmaxf(mx1, v1);
            mx2 = fmaxf(mx2, v2); mx3 = fmaxf(mx3, v3);
        }
    }
#pragma unroll
    for (int o = 16; o; o >>= 1) {
        mx0 = fmaxf(mx0, __shfl_xor_sync(0xFFFFFFFFu, mx0, o));
        mx1 = fmaxf(mx1, __shfl_xor_sync(0xFFFFFFFFu, mx1, o));
        mx2 = fmaxf(mx2, __shfl_xor_sync(0xFFFFFFFFu, mx2, o));
        mx3 = fmaxf(mx3, __shfl_xor_sync(0xFFFFFFFFu, mx3, o));
    }
    float s0 = 0.f, s1 = 0.f, s2 = 0.f, s3 = 0.f;
    if (have) {
        float a0 = __expf(c0 - mx0), a1 = __expf(c1 - mx1);
        float a2 = __expf(c2 - mx2), a3 = __expf(c3 - mx3);
        *(float4*)&g_e[(size_t)(beg + lane) * 4] = make_float4(a0, a1, a2, a3);
        s0 = a0; s1 = a1; s2 = a2; s3 = a3;
    }
    for (int base = 32; base < deg; base += 32) {
        int i = base + lane;
        if (i < deg) {
            int s = g_srcs[beg + i];
            float4 av = *(const float4*)&g_as[s * 4];
            float v0 = av.x + adv.x, v1 = av.y + adv.y;
            float v2 = av.z + adv.z, v3 = av.w + adv.w;
            v0 = v0 > 0.f ? v0 : 0.2f * v0;
            v1 = v1 > 0.f ? v1 : 0.2f * v1;
            v2 = v2 > 0.f ? v2 : 0.2f * v2;
            v3 = v3 > 0.f ? v3 : 0.2f * v3;
            float a0 = __expf(v0 - mx0), a1 = __expf(v1 - mx1);
            float a2 = __expf(v2 - mx2), a3 = __expf(v3 - mx3);
            *(float4*)&g_e[(size_t)(beg + i) * 4] = make_float4(a0, a1, a2, a3);
            s0 += a0; s1 += a1; s2 += a2; s3 += a3;
        }
    }
#pragma unroll
    for (int o = 16; o; o >>= 1) {
        s0 += __shfl_xor_sync(0xFFFFFFFFu, s0, o);
        s1 += __shfl_xor_sync(0xFFFFFFFFu, s1, o);
        s2 += __shfl_xor_sync(0xFFFFFFFFu, s2, o);
        s3 += __shfl_xor_sync(0xFFFFFFFFu, s3, o);
    }
    if (lane == 0)
        *(float4*)&g_r[node * 4] = make_float4(1.f / s0, 1.f / s1, 1.f / s2, 1.f / s3);
}

// ---------------- softmax coefs (H=1) ----------------------------------------
__global__ __launch_bounds__(256) void attn_coef1() {
    int node = (blockIdx.x * blockDim.x + threadIdx.x) >> 5;
    int lane = threadIdx.x & 31;
    if (node >= NN) return;
    int beg = g_off[node];
    int deg = g_off[node + 1] - beg;

    float adv = g_ad[node];
    float vc = 0.f;
    bool have = lane < deg;
    float mx = -1e30f;
    if (have) {
        int s = g_srcs[beg + lane];
        float v = g_as[s] + adv;
        vc = v > 0.f ? v : 0.2f * v;
        mx = vc;
    }
    for (int base = 32; base < deg; base += 32) {
        int i = base + lane;
        if (i < deg) {
            int s = g_srcs[beg + i];
            float v = g_as[s] + adv;
            v = v > 0.f ? v : 0.2f * v;
            mx = fmaxf(mx, v);
        }
    }
#pragma unroll
    for (int o = 16; o; o >>= 1) mx = fmaxf(mx, __shfl_xor_sync(0xFFFFFFFFu, mx, o));
    float sm = 0.f;
    if (have) {
        float a = __expf(vc - mx);
        g_e[beg + lane] = a;
        sm = a;
    }
    for (int base = 32; base < deg; base += 32) {
        int i = base + lane;
        if (i < deg) {
            int s = g_srcs[beg + i];
            float v = g_as[s] + adv;
            v = v > 0.f ? v : 0.2f * v;
            float a = __expf(v - mx);
            g_e[beg + i] = a;
            sm += a;
        }
    }
#pragma unroll
    for (int o = 16; o; o >>= 1) sm += __shfl_xor_sync(0xFFFFFFFFu, sm, o);
    if (lane == 0) g_r[node] = 1.f / sm;
}

// ---------------- aggregation: one warp per dst node, 256 channels ----------
__global__ __launch_bounds__(256) void aggr256(const float* __restrict__ h,
                                               const float* __restrict__ bias,
                                               float* __restrict__ obuf,
                                               int apply_elu) {
    int node = (blockIdx.x * blockDim.x + threadIdx.x) >> 5;
    int lane = threadIdx.x & 31;
    if (node >= NN) return;
    int beg = g_off[node];
    int deg = g_off[node + 1] - beg;
    int c  = lane * 8;
    int hd = lane >> 3;

    float4 a0 = make_float4(0.f, 0.f, 0.f, 0.f);
    float4 a1 = make_float4(0.f, 0.f, 0.f, 0.f);

    int sp = g_srcs[beg];                    // prefetch (deg >= 1 always)
    for (int i = 0; i < deg; i++) {
        int cs = sp;
        if (i + 1 < deg) sp = g_srcs[beg + i + 1];
        float4 cf = *(const float4*)&g_e[(size_t)(beg + i) * 4];
        float coef = hd == 0 ? cf.x : hd == 1 ? cf.y : hd == 2 ? cf.z : cf.w;
        const float4* hp = (const float4*)(h + (size_t)cs * 256 + c);
        float4 v0 = hp[0], v1 = hp[1];
        a0.x += coef * v0.x; a0.y += coef * v0.y;
        a0.z += coef * v0.z; a0.w += coef * v0.w;
        a1.x += coef * v1.x; a1.y += coef * v1.y;
        a1.z += coef * v1.z; a1.w += coef * v1.w;
    }
    float4 rv = *(const float4*)&g_r[node * 4];
    float r = hd == 0 ? rv.x : hd == 1 ? rv.y : hd == 2 ? rv.z : rv.w;
    float4 b0 = *(const float4*)&bias[c];
    float4 b1 = *(const float4*)&bias[c + 4];
    a0.x = a0.x * r + b0.x; a0.y = a0.y * r + b0.y;
    a0.z = a0.z * r + b0.z; a0.w = a0.w * r + b0.w;
    a1.x = a1.x * r + b1.x; a1.y = a1.y * r + b1.y;
    a1.z = a1.z * r + b1.z; a1.w = a1.w * r + b1.w;
    if (apply_elu) {
        a0.x = a0.x > 0.f ? a0.x : expm1f(a0.x);
        a0.y = a0.y > 0.f ? a0.y : expm1f(a0.y);
        a0.z = a0.z > 0.f ? a0.z : expm1f(a0.z);
        a0.w = a0.w > 0.f ? a0.w : expm1f(a0.w);
        a1.x = a1.x > 0.f ? a1.x : expm1f(a1.x);
        a1.y = a1.y > 0.f ? a1.y : expm1f(a1.y);
        a1.z = a1.z > 0.f ? a1.z : expm1f(a1.z);
        a1.w = a1.w > 0.f ? a1.w : expm1f(a1.w);
    }
    float4* op = (float4*)(obuf + (size_t)node * 256 + c);
    op[0] = a0;
    op[1] = a1;
}

// ---------------- aggregation, layer 3: 40 channels, H=1 ---------------------
__global__ __launch_bounds__(256) void aggr40(const float* __restrict__ h,
                                              const float* __restrict__ bias,
                                              float* __restrict__ out) {
    int node = (blockIdx.x * blockDim.x + threadIdx.x) >> 5;
    int lane = threadIdx.x & 31;
    if (node >= NN) return;
    int beg = g_off[node];
    int deg = g_off[node + 1] - beg;

    float4 acc = make_float4(0.f, 0.f, 0.f, 0.f);
    int c = lane * 4;
    bool act = lane < 10;

    int sp = g_srcs[beg];
    for (int i = 0; i < deg; i++) {
        int cs = sp;
        if (i + 1 < deg) sp = g_srcs[beg + i + 1];
        float coef = g_e[beg + i];
        if (act) {
            float4 v = *(const float4*)(h + (size_t)cs * 40 + c);
            acc.x += coef * v.x; acc.y += coef * v.y;
            acc.z += coef * v.z; acc.w += coef * v.w;
        }
    }
    if (act) {
        float r = g_r[node];
        float4 b = *(const float4*)&bias[c];
        acc.x = acc.x * r + b.x; acc.y = acc.y * r + b.y;
        acc.z = acc.z * r + b.z; acc.w = acc.w * r + b.w;
        *(float4*)(out + (size_t)node * 40 + c) = acc;
    }
}

// ---------------- driver ----------------------------------------------------
extern "C" void kernel_launch(void* const* d_in, const int* in_sizes, int n_in,
                              void* d_out, int out_size) {
    const float* x   = (const float*)d_in[0];
    const int*   ei  = (const int*)  d_in[1];
    const float* W1  = (const float*)d_in[2];
    const float* as1 = (const float*)d_in[3];
    const float* ad1 = (const float*)d_in[4];
    const float* b1  = (const float*)d_in[5];
    const float* W2  = (const float*)d_in[6];
    const float* as2 = (const float*)d_in[7];
    const float* ad2 = (const float*)d_in[8];
    const float* b2  = (const float*)d_in[9];
    const float* W3  = (const float*)d_in[10];
    const float* as3 = (const float*)d_in[11];
    const float* ad3 = (const float*)d_in[12];
    const float* b3  = (const float*)d_in[13];
    float* out = (float*)d_out;

    float *h, *buf;
    cudaGetSymbolAddress((void**)&h,   g_h);
    cudaGetSymbolAddress((void**)&buf, g_buf);

    const int TB = 256;
    int gE = (ETOT + TB - 1) / TB;
    int gW = (NN * 32 + TB - 1) / TB;   // one warp per node

    // ---- CSR by dst (edge structure shared by all layers) ----
    k_zero_deg<<<(NN + TB - 1) / TB, TB>>>();
    k_count  <<<gE, TB>>>(ei);
    k_scan   <<<1, 1024>>>();
    k_scatter<<<gE, TB>>>(ei);

    // ---- layer 1 ----
    dim3 g1((NN + 127) / 128, (D1 + 127) / 128);
    gemm_tf32 <<<g1, TB>>>(x, W1, h, NN, D1, FIN);
    node_prep <<<gW, TB>>>(h, as1, ad1, HEADS, HID);
    attn_coef4<<<gW, TB>>>();
    aggr256   <<<gW, TB>>>(h, b1, buf, 1);

    // ---- layer 2 ----
    gemm_tf32 <<<g1, TB>>>(buf, W2, h, NN, D1, D1);
    node_prep <<<gW, TB>>>(h, as2, ad2, HEADS, HID);
    attn_coef4<<<gW, TB>>>();
    aggr256   <<<gW, TB>>>(h, b2, buf, 1);

    // ---- layer 3 ----
    dim3 g3((NN + 127) / 128, 1);
    gemm_tf32 <<<g3, TB>>>(buf, W3, h, NN, NCLS, D1);
    node_prep <<<gW, TB>>>(h, as3, ad3, 1, NCLS);
    attn_coef1<<<gW, TB>>>();
    aggr40    <<<gW, TB>>>(h, b3, out);
}